// round 16
// baseline (speedup 1.0000x reference)
#include <cuda_runtime.h>
#include <cuda.h>
#include <cuda_fp16.h>
#include <cstdint>

// ---------------------------------------------------------------------------
// Geometry
// ---------------------------------------------------------------------------
#define MTOT 8192
#define DIN  4096
#define DOUT 4096

#define BM 128
#define BN 128
#define BK 64               // 64 fp16 = 128 B = one SW128 atom row
#define STAGES 3
#define KITERS (DIN / BK)   // 64

#define A_BYTES (BM * BK * 2)            // 16 KB
#define B_BYTES (BN * BK * 2)            // 16 KB
#define STG_BYTES (A_BYTES + B_BYTES)    // 32 KB
#define SMEM_A(s) (1024 + (s) * STG_BYTES)
#define SMEM_B(s) (SMEM_A(s) + A_BYTES)
#define SMEM_TOTAL (1024 + STAGES * STG_BYTES)   // 99328 B -> 2 CTAs/SM
#define MBAR(s) ((s) * 8)

// ---------------------------------------------------------------------------
// Scratch (__device__ globals: allocation-free)
// ---------------------------------------------------------------------------
static __device__ __half g_x16[(size_t)MTOT * DIN];   // x in fp16
static __device__ __half g_wq[(size_t)DOUT * DIN];    // integer weights in fp16
static __device__ float  g_scale[DOUT];               // row_norm / 127

// ---------------------------------------------------------------------------
// PTX helpers (base sm_90+ features only — NO tcgen05, toolchain targets sm_103)
// ---------------------------------------------------------------------------
__device__ __forceinline__ uint32_t smem_u32(const void* p) {
    return (uint32_t)__cvta_generic_to_shared(p);
}

#define MBARRIER_INIT(addr, count) \
    asm volatile("mbarrier.init.shared.b64 [%0], %1;" :: "r"((uint32_t)(addr)), "r"((uint32_t)(count)) : "memory")

#define MBARRIER_EXPECT_TX(addr, bytes) \
    asm volatile("mbarrier.arrive.expect_tx.shared.b64 _, [%0], %1;" :: "r"((uint32_t)(addr)), "r"((uint32_t)(bytes)) : "memory")

#define MBARRIER_WAIT_PARITY(mbar_smem_addr, phase_parity) do { \
    uint32_t _mbar = (uint32_t)(mbar_smem_addr); \
    uint32_t _parity = (uint32_t)(phase_parity); \
    uint32_t _done; \
    asm volatile( \
        "{\n\t.reg .pred p;\n\t" \
        "mbarrier.try_wait.parity.acquire.cta.shared::cta.b64 p, [%1], %2;\n\t" \
        "selp.b32 %0, 1, 0, p;\n\t}" \
        : "=r"(_done) : "r"(_mbar), "r"(_parity) : "memory"); \
    if (!_done) { \
        asm volatile( \
            "{\n\t.reg .pred P1;\n\t" \
            "WAIT_LOOP_%=:\n\t" \
            "mbarrier.try_wait.parity.acquire.cta.shared::cta.b64 P1, [%0], %1, 0x989680;\n\t" \
            "@P1 bra.uni WAIT_DONE_%=;\n\t" \
            "bra.uni WAIT_LOOP_%=;\n\t" \
            "WAIT_DONE_%=:\n\t}" \
            :: "r"(_mbar), "r"(_parity) : "memory"); \
    } \
} while (0)

#define TMA_LOAD_3D(smem_addr, tensor_map, cx, cy, cz, mbar) \
    asm volatile( \
        "cp.async.bulk.tensor.3d.shared::cta.global.tile.mbarrier::complete_tx::bytes " \
        "[%0], [%1, {%2, %3, %4}], [%5];" \
        :: "r"((uint32_t)(smem_addr)), "l"(tensor_map), \
           "r"((int32_t)(cx)), "r"((int32_t)(cy)), "r"((int32_t)(cz)), \
           "r"((uint32_t)(mbar)) \
        : "memory")

__device__ __forceinline__ void ldsm4(uint32_t* r, uint32_t addr) {
    asm volatile("ldmatrix.sync.aligned.m8n8.x4.shared.b16 {%0,%1,%2,%3}, [%4];"
                 : "=r"(r[0]), "=r"(r[1]), "=r"(r[2]), "=r"(r[3]) : "r"(addr));
}

__device__ __forceinline__ void mma16816(float* d, const uint32_t* a, uint32_t b0, uint32_t b1) {
    asm volatile("mma.sync.aligned.m16n8k16.row.col.f32.f16.f16.f32 "
                 "{%0,%1,%2,%3}, {%4,%5,%6,%7}, {%8,%9}, {%0,%1,%2,%3};"
                 : "+f"(d[0]), "+f"(d[1]), "+f"(d[2]), "+f"(d[3])
                 : "r"(a[0]), "r"(a[1]), "r"(a[2]), "r"(a[3]), "r"(b0), "r"(b1));
}

// SW128 swizzle: bits [4:6] ^= bits [7:9]
__device__ __forceinline__ int sw128(int off) { return off ^ ((off >> 3) & 0x70); }

// ---------------------------------------------------------------------------
// Fused prep: blocks [0,4096) quantize W rows (single pass, row in registers);
//             blocks [4096,8192) convert x fp32 -> fp16.
// ---------------------------------------------------------------------------
__global__ __launch_bounds__(256) void prep_fused_kernel(const float* __restrict__ W,
                                                         const float4* __restrict__ x) {
    int b = blockIdx.x;
    if (b < DOUT) {
        const float4* wr4 = (const float4*)(W + (size_t)b * DIN);
        float4 v[4];
        float ss = 0.0f;
#pragma unroll
        for (int it = 0; it < 4; it++) {
            v[it] = __ldg(&wr4[it * 256 + threadIdx.x]);
            ss += v[it].x * v[it].x + v[it].y * v[it].y
                + v[it].z * v[it].z + v[it].w * v[it].w;
        }
        for (int o = 16; o; o >>= 1) ss += __shfl_xor_sync(0xffffffffu, ss, o);

        __shared__ float red[8];
        __shared__ float s_norm;
        int wid = threadIdx.x >> 5, lid = threadIdx.x & 31;
        if (lid == 0) red[wid] = ss;
        __syncthreads();
        if (wid == 0) {
            float tot = (lid < 8) ? red[lid] : 0.0f;
            for (int o = 4; o; o >>= 1) tot += __shfl_xor_sync(0xffffffffu, tot, o);
            if (lid == 0) {
                float n = sqrtf(tot);
                s_norm = n;
                g_scale[b] = n * (1.0f / 127.0f);
            }
        }
        __syncthreads();

        float inv = 1.0f / (s_norm + 1e-8f);
        __half* dst = g_wq + (size_t)b * DIN;
#pragma unroll
        for (int it = 0; it < 4; it++) {
            int i = it * 256 + threadIdx.x;
            float f[4] = {v[it].x, v[it].y, v[it].z, v[it].w};
            __half h[4];
#pragma unroll
            for (int j = 0; j < 4; j++) {
                float wn = f[j] * inv;
                wn = fminf(fmaxf(wn, -1.0f), 1.0f);
                h[j] = __float2half_rn(rintf(wn * 127.0f));   // integer, exact fp16
            }
            *(uint2*)&dst[(size_t)i * 4] = *(uint2*)h;
        }
    } else {
        int base = (b - DOUT) * 2048;
#pragma unroll
        for (int it = 0; it < 8; it++) {
            int i = base + it * 256 + threadIdx.x;
            float4 v = __ldg(&x[i]);
            __half h[4];
            h[0] = __float2half_rn(v.x);
            h[1] = __float2half_rn(v.y);
            h[2] = __float2half_rn(v.z);
            h[3] = __float2half_rn(v.w);
            *(uint2*)&g_x16[(size_t)i * 4] = *(uint2*)h;
        }
    }
}

// ---------------------------------------------------------------------------
// GEMM: 2 CTAs/SM (4 warps/SMSP), 3-stage TMA ring, 8 warps/CTA,
// warp tile 64x32, 2-deep fragment software pipeline (R8 mechanism at R5
// occupancy — the only untested combination).
// ---------------------------------------------------------------------------
__global__ __launch_bounds__(256, 2)
void gemm_kernel(float* __restrict__ out,
                 const float* __restrict__ bias,
                 const __grid_constant__ CUtensorMap tmA,
                 const __grid_constant__ CUtensorMap tmB) {
    extern __shared__ char smem[];
    uint32_t sb = smem_u32(smem);
    int tid = threadIdx.x;
    int wid = tid >> 5, lid = tid & 31;
    int warp_m = wid & 1;        // 2 rows of 64
    int warp_n = wid >> 1;       // 4 cols of 32

    int n0 = blockIdx.x * BN;    // gridDim.x = 32 (n fastest: W strip L2-shared)
    int m0 = blockIdx.y * BM;

    if (tid == 0) {
        for (int s = 0; s < STAGES; s++) MBARRIER_INIT(sb + MBAR(s), 1);
    }
    __syncthreads();

    if (tid == 0) {
#pragma unroll
        for (int s = 0; s < STAGES; s++) {
            MBARRIER_EXPECT_TX(sb + MBAR(s), STG_BYTES);
            TMA_LOAD_3D(sb + SMEM_A(s), &tmA, s * BK, m0, 0, sb + MBAR(s));
            TMA_LOAD_3D(sb + SMEM_B(s), &tmB, s * BK, n0, 0, sb + MBAR(s));
        }
    }

    float acc[4][4][4];
#pragma unroll
    for (int i = 0; i < 4; i++)
#pragma unroll
        for (int j = 0; j < 4; j++)
#pragma unroll
            for (int r = 0; r < 4; r++) acc[i][j][r] = 0.0f;

    uint32_t afrag[2][4][4], bfrag[2][2][4];

    // per-lane ldmatrix row components (constant across k)
    int a_row = warp_m * 64 + (lid & 15);      // + mi*16
    int b_row = warp_n * 32 + (lid & 15);      // + ni2*16
    int colb0 = (lid >> 4) * 16;               // + ks*32

    auto LOADF = [&](int buf, uint32_t a_base, uint32_t b_base, int ks) {
#pragma unroll
        for (int mi = 0; mi < 4; mi++)
            ldsm4(afrag[buf][mi], a_base + sw128((a_row + mi * 16) * 128 + ks * 32 + colb0));
#pragma unroll
        for (int ni2 = 0; ni2 < 2; ni2++)
            ldsm4(bfrag[buf][ni2], b_base + sw128((b_row + ni2 * 16) * 128 + ks * 32 + colb0));
    };
    auto MMAS = [&](int buf) {
#pragma unroll
        for (int mi = 0; mi < 4; mi++)
#pragma unroll
            for (int ni = 0; ni < 4; ni++) {
                int ni2 = ni >> 1, sub = ni & 1;
                mma16816(acc[mi][ni], afrag[buf][mi],
                         bfrag[buf][ni2][sub], bfrag[buf][ni2][sub + 2]);
            }
    };

    // prologue: stage 0 ready -> load ks0 into buffer 0
    MBARRIER_WAIT_PARITY(sb + MBAR(0), 0);
    LOADF(0, sb + SMEM_A(0), sb + SMEM_B(0), 0);

    int st = 0, ph = 0;
    for (int kt = 0; kt < KITERS; kt++) {
        uint32_t a_base = sb + SMEM_A(st);
        uint32_t b_base = sb + SMEM_B(st);

        // ks = 0..2: prefetch ks+1, compute ks (buffers alternate 0,1,0,1)
#pragma unroll
        for (int ks = 0; ks < 3; ks++) {
            LOADF((ks & 1) ^ 1, a_base, b_base, ks + 1);
            MMAS(ks & 1);
        }

        // ks = 3 lives in buffer 1; prefetch next stage's ks0 into buffer 0 first
        int nst = (st + 1 == STAGES) ? 0 : st + 1;
        int nph = (st + 1 == STAGES) ? ph ^ 1 : ph;
        if (kt + 1 < KITERS) {
            MBARRIER_WAIT_PARITY(sb + MBAR(nst), nph);
            LOADF(0, sb + SMEM_A(nst), sb + SMEM_B(nst), 0);
        }
        MMAS(1);

        // release stage st (last smem read of st was ks=3 prefetch at ks=2 iter)
        __syncthreads();
        if (tid == 0 && kt + STAGES < KITERS) {
            MBARRIER_EXPECT_TX(sb + MBAR(st), STG_BYTES);
            TMA_LOAD_3D(sb + SMEM_A(st), &tmA, (kt + STAGES) * BK, m0, 0, sb + MBAR(st));
            TMA_LOAD_3D(sb + SMEM_B(st), &tmB, (kt + STAGES) * BK, n0, 0, sb + MBAR(st));
        }
        st = nst; ph = nph;
    }

    // ---- epilogue: out = acc * scale[n] + bias[n] ----
    int qrow = lid >> 2;           // 0..7
    int qcol = 2 * (lid & 3);      // 0,2,4,6
#pragma unroll
    for (int mi = 0; mi < 4; mi++) {
        int m_lo = m0 + warp_m * 64 + mi * 16 + qrow;
#pragma unroll
        for (int ni = 0; ni < 4; ni++) {
            int n = n0 + warp_n * 32 + ni * 8 + qcol;
            float2 sc = __ldg((const float2*)(g_scale + n));
            float2 bi = __ldg((const float2*)(bias + n));
            const float* d = acc[mi][ni];
            float2 o0, o1;
            o0.x = d[0] * sc.x + bi.x;
            o0.y = d[1] * sc.y + bi.y;
            o1.x = d[2] * sc.x + bi.x;
            o1.y = d[3] * sc.y + bi.y;
            *(float2*)(out + (size_t)m_lo * DOUT + n)       = o0;
            *(float2*)(out + (size_t)(m_lo + 8) * DOUT + n) = o1;
        }
    }
}

// ---------------------------------------------------------------------------
// Host launch
// ---------------------------------------------------------------------------
typedef CUresult (CUDAAPI *TMEncodeFn)(
    CUtensorMap*, CUtensorMapDataType, cuuint32_t, void*,
    const cuuint64_t*, const cuuint64_t*, const cuuint32_t*, const cuuint32_t*,
    CUtensorMapInterleave, CUtensorMapSwizzle, CUtensorMapL2promotion, CUtensorMapFloatOOBfill);

extern "C" void kernel_launch(void* const* d_in, const int* in_sizes, int n_in,
                              void* d_out, int out_size) {
    const float* x    = (const float*)d_in[0];
    const float* W    = (const float*)d_in[1];
    const float* bias = (const float*)d_in[2];
    float* out        = (float*)d_out;

    void* x16_ptr = nullptr;
    void* wq_ptr  = nullptr;
    cudaGetSymbolAddress(&x16_ptr, g_x16);
    cudaGetSymbolAddress(&wq_ptr, g_wq);

    TMEncodeFn enc = nullptr;
    cudaDriverEntryPointQueryResult qres;
    cudaGetDriverEntryPoint("cuTensorMapEncodeTiled", (void**)&enc, cudaEnableDefault, &qres);

    CUtensorMap tmA, tmB;
    {   // A: fp16 [MTOT][DIN], box (BK, BM), SW128
        cuuint64_t dims[3]    = {DIN, MTOT, 1};
        cuuint64_t strides[2] = {(cuuint64_t)DIN * 2, (cuuint64_t)MTOT * DIN * 2};
        cuuint32_t box[3]     = {BK, BM, 1};
        cuuint32_t es[3]      = {1, 1, 1};
        enc(&tmA, CU_TENSOR_MAP_DATA_TYPE_FLOAT16, 3, x16_ptr, dims, strides, box, es,
            CU_TENSOR_MAP_INTERLEAVE_NONE, CU_TENSOR_MAP_SWIZZLE_128B,
            CU_TENSOR_MAP_L2_PROMOTION_L2_128B, CU_TENSOR_MAP_FLOAT_OOB_FILL_NONE);
    }
    {   // B: fp16 [DOUT][DIN], box (BK, BN), SW128
        cuuint64_t dims[3]    = {DIN, DOUT, 1};
        cuuint64_t strides[2] = {(cuuint64_t)DIN * 2, (cuuint64_t)DOUT * DIN * 2};
        cuuint32_t box[3]     = {BK, BN, 1};
        cuuint32_t es[3]      = {1, 1, 1};
        enc(&tmB, CU_TENSOR_MAP_DATA_TYPE_FLOAT16, 3, wq_ptr, dims, strides, box, es,
            CU_TENSOR_MAP_INTERLEAVE_NONE, CU_TENSOR_MAP_SWIZZLE_128B,
            CU_TENSOR_MAP_L2_PROMOTION_L2_128B, CU_TENSOR_MAP_FLOAT_OOB_FILL_NONE);
    }

    cudaFuncSetAttribute(gemm_kernel, cudaFuncAttributeMaxDynamicSharedMemorySize, SMEM_TOTAL);

    prep_fused_kernel<<<8192, 256>>>(W, (const float4*)x);

    dim3 grid(DOUT / BN, MTOT / BM);   // 32 x 64
    gemm_kernel<<<grid, 256, SMEM_TOTAL>>>(out, bias, tmA, tmB);
}

// round 17
// speedup vs baseline: 1.0712x; 1.0712x over previous
#include <cuda_runtime.h>
#include <cuda.h>
#include <cuda_fp16.h>
#include <cstdint>

// ---------------------------------------------------------------------------
// Geometry
// ---------------------------------------------------------------------------
#define MTOT 8192
#define DIN  4096
#define DOUT 4096

#define BM 128
#define BN 256
#define BK 64               // 64 fp16 = 128 B = one SW128 atom row
#define STAGES 4
#define KITERS (DIN / BK)   // 64
#define PAIRS  (KITERS / 2) // 32

#define A_BYTES (BM * BK * 2)            // 16 KB
#define B_BYTES (BN * BK * 2)            // 32 KB
#define STG_BYTES (A_BYTES + B_BYTES)    // 48 KB
#define SMEM_A(s) (1024 + (s) * STG_BYTES)
#define SMEM_B(s) (SMEM_A(s) + A_BYTES)
#define SMEM_TOTAL (1024 + STAGES * STG_BYTES)   // 197632 B, 1 CTA/SM
#define PBAR(p) ((p) * 8)                // one barrier per stage PAIR

// ---------------------------------------------------------------------------
// Scratch (__device__ globals: allocation-free)
// ---------------------------------------------------------------------------
static __device__ __half g_x16[(size_t)MTOT * DIN];   // x in fp16
static __device__ __half g_wq[(size_t)DOUT * DIN];    // integer weights in fp16
static __device__ float  g_scale[DOUT];               // row_norm / 127

// ---------------------------------------------------------------------------
// PTX helpers (base sm_90+ features only — NO tcgen05, toolchain targets sm_103)
// ---------------------------------------------------------------------------
__device__ __forceinline__ uint32_t smem_u32(const void* p) {
    return (uint32_t)__cvta_generic_to_shared(p);
}

#define MBARRIER_INIT(addr, count) \
    asm volatile("mbarrier.init.shared.b64 [%0], %1;" :: "r"((uint32_t)(addr)), "r"((uint32_t)(count)) : "memory")

#define MBARRIER_EXPECT_TX(addr, bytes) \
    asm volatile("mbarrier.arrive.expect_tx.shared.b64 _, [%0], %1;" :: "r"((uint32_t)(addr)), "r"((uint32_t)(bytes)) : "memory")

#define MBARRIER_WAIT_PARITY(mbar_smem_addr, phase_parity) do { \
    uint32_t _mbar = (uint32_t)(mbar_smem_addr); \
    uint32_t _parity = (uint32_t)(phase_parity); \
    uint32_t _done; \
    asm volatile( \
        "{\n\t.reg .pred p;\n\t" \
        "mbarrier.try_wait.parity.acquire.cta.shared::cta.b64 p, [%1], %2;\n\t" \
        "selp.b32 %0, 1, 0, p;\n\t}" \
        : "=r"(_done) : "r"(_mbar), "r"(_parity) : "memory"); \
    if (!_done) { \
        asm volatile( \
            "{\n\t.reg .pred P1;\n\t" \
            "WAIT_LOOP_%=:\n\t" \
            "mbarrier.try_wait.parity.acquire.cta.shared::cta.b64 P1, [%0], %1, 0x989680;\n\t" \
            "@P1 bra.uni WAIT_DONE_%=;\n\t" \
            "bra.uni WAIT_LOOP_%=;\n\t" \
            "WAIT_DONE_%=:\n\t}" \
            :: "r"(_mbar), "r"(_parity) : "memory"); \
    } \
} while (0)

#define TMA_LOAD_3D(smem_addr, tensor_map, cx, cy, cz, mbar) \
    asm volatile( \
        "cp.async.bulk.tensor.3d.shared::cta.global.tile.mbarrier::complete_tx::bytes " \
        "[%0], [%1, {%2, %3, %4}], [%5];" \
        :: "r"((uint32_t)(smem_addr)), "l"(tensor_map), \
           "r"((int32_t)(cx)), "r"((int32_t)(cy)), "r"((int32_t)(cz)), \
           "r"((uint32_t)(mbar)) \
        : "memory")

__device__ __forceinline__ void ldsm4(uint32_t* r, uint32_t addr) {
    asm volatile("ldmatrix.sync.aligned.m8n8.x4.shared.b16 {%0,%1,%2,%3}, [%4];"
                 : "=r"(r[0]), "=r"(r[1]), "=r"(r[2]), "=r"(r[3]) : "r"(addr));
}

__device__ __forceinline__ void mma16816(float* d, const uint32_t* a, uint32_t b0, uint32_t b1) {
    asm volatile("mma.sync.aligned.m16n8k16.row.col.f32.f16.f16.f32 "
                 "{%0,%1,%2,%3}, {%4,%5,%6,%7}, {%8,%9}, {%0,%1,%2,%3};"
                 : "+f"(d[0]), "+f"(d[1]), "+f"(d[2]), "+f"(d[3])
                 : "r"(a[0]), "r"(a[1]), "r"(a[2]), "r"(a[3]), "r"(b0), "r"(b1));
}

// SW128 swizzle: bits [4:6] ^= bits [7:9]
__device__ __forceinline__ int sw128(int off) { return off ^ ((off >> 3) & 0x70); }

// ---------------------------------------------------------------------------
// Fused prep: blocks [0,4096) quantize W rows (single pass, row in registers);
//             blocks [4096,8192) convert x fp32 -> fp16.
// ---------------------------------------------------------------------------
__global__ __launch_bounds__(256) void prep_fused_kernel(const float* __restrict__ W,
                                                         const float4* __restrict__ x) {
    int b = blockIdx.x;
    if (b < DOUT) {
        const float4* wr4 = (const float4*)(W + (size_t)b * DIN);
        float4 v[4];
        float ss = 0.0f;
#pragma unroll
        for (int it = 0; it < 4; it++) {
            v[it] = __ldg(&wr4[it * 256 + threadIdx.x]);
            ss += v[it].x * v[it].x + v[it].y * v[it].y
                + v[it].z * v[it].z + v[it].w * v[it].w;
        }
        for (int o = 16; o; o >>= 1) ss += __shfl_xor_sync(0xffffffffu, ss, o);

        __shared__ float red[8];
        __shared__ float s_norm;
        int wid = threadIdx.x >> 5, lid = threadIdx.x & 31;
        if (lid == 0) red[wid] = ss;
        __syncthreads();
        if (wid == 0) {
            float tot = (lid < 8) ? red[lid] : 0.0f;
            for (int o = 4; o; o >>= 1) tot += __shfl_xor_sync(0xffffffffu, tot, o);
            if (lid == 0) {
                float n = sqrtf(tot);
                s_norm = n;
                g_scale[b] = n * (1.0f / 127.0f);
            }
        }
        __syncthreads();

        float inv = 1.0f / (s_norm + 1e-8f);
        __half* dst = g_wq + (size_t)b * DIN;
#pragma unroll
        for (int it = 0; it < 4; it++) {
            int i = it * 256 + threadIdx.x;
            float f[4] = {v[it].x, v[it].y, v[it].z, v[it].w};
            __half h[4];
#pragma unroll
            for (int j = 0; j < 4; j++) {
                float wn = f[j] * inv;
                wn = fminf(fmaxf(wn, -1.0f), 1.0f);
                h[j] = __float2half_rn(rintf(wn * 127.0f));   // round-half-even, exact fp16 int
            }
            *(uint2*)&dst[(size_t)i * 4] = *(uint2*)h;
        }
    } else {
        int base = (b - DOUT) * 2048;
#pragma unroll
        for (int it = 0; it < 8; it++) {
            int i = base + it * 256 + threadIdx.x;
            float4 v = __ldg(&x[i]);
            __half h[4];
            h[0] = __float2half_rn(v.x);
            h[1] = __float2half_rn(v.y);
            h[2] = __float2half_rn(v.z);
            h[3] = __float2half_rn(v.w);
            *(uint2*)&g_x16[(size_t)i * 4] = *(uint2*)h;
        }
    }
}

// ---------------------------------------------------------------------------
// GEMM: 1 CTA/SM, 4-stage TMA ring with PAIRED barriers (1 wait per 2 kt),
// 8 warps, warp tile 64x64, 2-deep fragment software pipeline.
// (R9 — measured champion: 604.2 us total, tensor 80.4%)
// ---------------------------------------------------------------------------
__global__ __launch_bounds__(256, 1)
void gemm_kernel(float* __restrict__ out,
                 const float* __restrict__ bias,
                 const __grid_constant__ CUtensorMap tmA,
                 const __grid_constant__ CUtensorMap tmB) {
    extern __shared__ char smem[];
    uint32_t sb = smem_u32(smem);
    int tid = threadIdx.x;
    int wid = tid >> 5, lid = tid & 31;
    int warp_m = wid & 1;        // 2 rows of 64
    int warp_n = wid >> 1;       // 4 cols of 64

    int n0 = blockIdx.x * BN;    // gridDim.x = 16 (n fastest: W strip L2-shared)
    int m0 = blockIdx.y * BM;

    if (tid == 0) {
        MBARRIER_INIT(sb + PBAR(0), 1);
        MBARRIER_INIT(sb + PBAR(1), 1);
    }
    __syncthreads();

    if (tid == 0) {
#pragma unroll
        for (int p = 0; p < 2; p++) {
            MBARRIER_EXPECT_TX(sb + PBAR(p), 2 * STG_BYTES);
#pragma unroll
            for (int j = 0; j < 2; j++) {
                int s = 2 * p + j;
                TMA_LOAD_3D(sb + SMEM_A(s), &tmA, s * BK, m0, 0, sb + PBAR(p));
                TMA_LOAD_3D(sb + SMEM_B(s), &tmB, s * BK, n0, 0, sb + PBAR(p));
            }
        }
    }

    float acc[4][8][4];
#pragma unroll
    for (int i = 0; i < 4; i++)
#pragma unroll
        for (int j = 0; j < 8; j++)
#pragma unroll
            for (int r = 0; r < 4; r++) acc[i][j][r] = 0.0f;

    uint32_t afrag[2][4][4], bfrag[2][4][4];

    // per-lane ldmatrix row components (constant across k)
    int a_row = warp_m * 64 + (lid & 15);      // + mi*16
    int b_row = warp_n * 64 + (lid & 15);      // + ni2*16
    int colb0 = (lid >> 4) * 16;               // + ks*32

    auto LOADF = [&](int buf, uint32_t a_base, uint32_t b_base, int ks) {
#pragma unroll
        for (int mi = 0; mi < 4; mi++)
            ldsm4(afrag[buf][mi], a_base + sw128((a_row + mi * 16) * 128 + ks * 32 + colb0));
#pragma unroll
        for (int ni2 = 0; ni2 < 4; ni2++)
            ldsm4(bfrag[buf][ni2], b_base + sw128((b_row + ni2 * 16) * 128 + ks * 32 + colb0));
    };
    auto MMAS = [&](int buf) {
#pragma unroll
        for (int mi = 0; mi < 4; mi++)
#pragma unroll
            for (int ni = 0; ni < 8; ni++) {
                int ni2 = ni >> 1, sub = ni & 1;
                mma16816(acc[mi][ni], afrag[buf][mi],
                         bfrag[buf][ni2][sub], bfrag[buf][ni2][sub + 2]);
            }
    };

    // prologue: pair 0 ready -> load stage0/ks0 into buffer 0
    MBARRIER_WAIT_PARITY(sb + PBAR(0), 0);
    LOADF(0, sb + SMEM_A(0), sb + SMEM_B(0), 0);

    for (int q = 0; q < PAIRS; q++) {            // pair index; stages 2*(q&1), +1
        int st0 = (q & 1) * 2;
        uint32_t aB[2] = {sb + (uint32_t)SMEM_A(st0), sb + (uint32_t)SMEM_A(st0 + 1)};
        uint32_t bB[2] = {sb + (uint32_t)SMEM_B(st0), sb + (uint32_t)SMEM_B(st0 + 1)};

        // gk = 0..7 across the pair (stage = gk>>2, ks = gk&3), buffers alternate
#pragma unroll
        for (int gk = 0; gk < 7; gk++) {
            int nk = gk + 1;
            LOADF((gk & 1) ^ 1, aB[nk >> 2], bB[nk >> 2], nk & 3);
            MMAS(gk & 1);
        }

        // last step (gk=7, buffer 1): first prefetch next pair's gk0 into buffer 0
        if (q + 1 < PAIRS) {
            int nb = (q + 1) & 1;
            MBARRIER_WAIT_PARITY(sb + PBAR(nb), ((q + 1) >> 1) & 1);
            int nst0 = nb * 2;
            LOADF(0, sb + SMEM_A(nst0), sb + SMEM_B(nst0), 0);
        }
        MMAS(1);

        // release this pair's stages and refill them for pair q+2
        __syncthreads();
        if (tid == 0 && q + 2 < PAIRS) {
            int p = q & 1;
            int kt = (q + 2) * 2;                // kt index for stage st0
            MBARRIER_EXPECT_TX(sb + PBAR(p), 2 * STG_BYTES);
            TMA_LOAD_3D(sb + SMEM_A(st0),     &tmA, kt * BK,       m0, 0, sb + PBAR(p));
            TMA_LOAD_3D(sb + SMEM_B(st0),     &tmB, kt * BK,       n0, 0, sb + PBAR(p));
            TMA_LOAD_3D(sb + SMEM_A(st0 + 1), &tmA, (kt + 1) * BK, m0, 0, sb + PBAR(p));
            TMA_LOAD_3D(sb + SMEM_B(st0 + 1), &tmB, (kt + 1) * BK, n0, 0, sb + PBAR(p));
        }
    }

    // ---- epilogue: out = acc * scale[n] + bias[n] ----
    int qrow = lid >> 2;           // 0..7
    int qcol = 2 * (lid & 3);      // 0,2,4,6
#pragma unroll
    for (int mi = 0; mi < 4; mi++) {
        int m_lo = m0 + warp_m * 64 + mi * 16 + qrow;
#pragma unroll
        for (int ni = 0; ni < 8; ni++) {
            int n = n0 + warp_n * 64 + ni * 8 + qcol;
            float2 sc = __ldg((const float2*)(g_scale + n));
            float2 bi = __ldg((const float2*)(bias + n));
            const float* d = acc[mi][ni];
            float2 o0, o1;
            o0.x = d[0] * sc.x + bi.x;
            o0.y = d[1] * sc.y + bi.y;
            o1.x = d[2] * sc.x + bi.x;
            o1.y = d[3] * sc.y + bi.y;
            *(float2*)(out + (size_t)m_lo * DOUT + n)       = o0;
            *(float2*)(out + (size_t)(m_lo + 8) * DOUT + n) = o1;
        }
    }
}

// ---------------------------------------------------------------------------
// Host launch
// ---------------------------------------------------------------------------
typedef CUresult (CUDAAPI *TMEncodeFn)(
    CUtensorMap*, CUtensorMapDataType, cuuint32_t, void*,
    const cuuint64_t*, const cuuint64_t*, const cuuint32_t*, const cuuint32_t*,
    CUtensorMapInterleave, CUtensorMapSwizzle, CUtensorMapL2promotion, CUtensorMapFloatOOBfill);

extern "C" void kernel_launch(void* const* d_in, const int* in_sizes, int n_in,
                              void* d_out, int out_size) {
    const float* x    = (const float*)d_in[0];
    const float* W    = (const float*)d_in[1];
    const float* bias = (const float*)d_in[2];
    float* out        = (float*)d_out;

    void* x16_ptr = nullptr;
    void* wq_ptr  = nullptr;
    cudaGetSymbolAddress(&x16_ptr, g_x16);
    cudaGetSymbolAddress(&wq_ptr, g_wq);

    TMEncodeFn enc = nullptr;
    cudaDriverEntryPointQueryResult qres;
    cudaGetDriverEntryPoint("cuTensorMapEncodeTiled", (void**)&enc, cudaEnableDefault, &qres);

    CUtensorMap tmA, tmB;
    {   // A: fp16 [MTOT][DIN], box (BK, BM), SW128
        cuuint64_t dims[3]    = {DIN, MTOT, 1};
        cuuint64_t strides[2] = {(cuuint64_t)DIN * 2, (cuuint64_t)MTOT * DIN * 2};
        cuuint32_t box[3]     = {BK, BM, 1};
        cuuint32_t es[3]      = {1, 1, 1};
        enc(&tmA, CU_TENSOR_MAP_DATA_TYPE_FLOAT16, 3, x16_ptr, dims, strides, box, es,
            CU_TENSOR_MAP_INTERLEAVE_NONE, CU_TENSOR_MAP_SWIZZLE_128B,
            CU_TENSOR_MAP_L2_PROMOTION_L2_128B, CU_TENSOR_MAP_FLOAT_OOB_FILL_NONE);
    }
    {   // B: fp16 [DOUT][DIN], box (BK, BN), SW128
        cuuint64_t dims[3]    = {DIN, DOUT, 1};
        cuuint64_t strides[2] = {(cuuint64_t)DIN * 2, (cuuint64_t)DOUT * DIN * 2};
        cuuint32_t box[3]     = {BK, BN, 1};
        cuuint32_t es[3]      = {1, 1, 1};
        enc(&tmB, CU_TENSOR_MAP_DATA_TYPE_FLOAT16, 3, wq_ptr, dims, strides, box, es,
            CU_TENSOR_MAP_INTERLEAVE_NONE, CU_TENSOR_MAP_SWIZZLE_128B,
            CU_TENSOR_MAP_L2_PROMOTION_L2_128B, CU_TENSOR_MAP_FLOAT_OOB_FILL_NONE);
    }

    cudaFuncSetAttribute(gemm_kernel, cudaFuncAttributeMaxDynamicSharedMemorySize, SMEM_TOTAL);

    prep_fused_kernel<<<8192, 256>>>(W, (const float4*)x);

    dim3 grid(DOUT / BN, MTOT / BM);   // 16 x 64
    gemm_kernel<<<grid, 256, SMEM_TOTAL>>>(out, bias, tmA, tmB);
}